// round 10
// baseline (speedup 1.0000x reference)
#include <cuda_runtime.h>
#include <cstdint>
#include <math.h>

#define NN 100000
#define FI 128
#define H  64
#define TE 128   // edges per block in k_edge

typedef unsigned long long u64;

__device__ __forceinline__ u64 ffma2(u64 a, u64 b, u64 c) {
    u64 d;
    asm("fma.rn.f32x2 %0, %1, %2, %3;" : "=l"(d) : "l"(a), "l"(b), "l"(c));
    return d;
}
__device__ __forceinline__ float2 unpack2(u64 p) {
    float2 f;
    asm("mov.b64 {%0,%1}, %2;" : "=f"(f.x), "=f"(f.y) : "l"(p));
    return f;
}
__device__ __forceinline__ u64 pack2(float lo, float hi) {
    u64 p;
    asm("mov.b64 %0, {%1,%2};" : "=l"(p) : "f"(lo), "f"(hi));
    return p;
}

// Scratch (device globals). 16B-aligned for float4 access.
__device__ __align__(16) float g_xl[(size_t)NN * H];
__device__ __align__(16) float g_xb[(size_t)NN * H];
__device__ __align__(16) float g_s [(size_t)NN * H];
__device__ __align__(16) float g_cnt[NN];
__device__ __align__(16) float g_hq[(size_t)NN * H];
__device__ __align__(16) float g_W2o[H * H];
__device__ __align__(16) float g_b2o[H];

// ---------------------------------------------------------------- prep (parallel)
__global__ void k_prep(const float* __restrict__ We2, const float* __restrict__ Wo1,
                       const float* __restrict__ be2, const float* __restrict__ bo1) {
    int j = threadIdx.x;
    int b = blockIdx.x;
    if (b < H) {
        float acc = 0.f;
        #pragma unroll 8
        for (int k = 0; k < H; k++) acc += We2[b * H + k] * Wo1[k * H + j];
        g_W2o[b * H + j] = acc;
    } else {
        float acc = bo1[j];
        #pragma unroll 8
        for (int k = 0; k < H; k++) acc += be2[k] * Wo1[k * H + j];
        g_b2o[j] = acc;
    }
}

// ------------------------------------------------- fused node linear: xl = x@Wl, xb = x@Wr + bl
// 64 nodes/block, 256 threads; thread = 4 nodes x 4 j; x staged transposed. (R8 form)
__global__ void __launch_bounds__(256) k_node_dual(const float* __restrict__ x,
                                                   const float* __restrict__ Wl,
                                                   const float* __restrict__ Wr,
                                                   const float* __restrict__ bl, int N) {
    extern __shared__ float sm[];
    float* xT = sm;                 // [128][64]  32KB
    float* wl = sm + FI * 64;       // [128][64]  32KB
    float* wr = wl + FI * H;        // [128][64]  32KB
    int tid = threadIdx.x;
    #pragma unroll
    for (int i = 0; i < 8; i++) {
        ((float4*)wl)[tid + i * 256] = ((const float4*)Wl)[tid + i * 256];
        ((float4*)wr)[tid + i * 256] = ((const float4*)Wr)[tid + i * 256];
    }
    int n_l = tid & 63, q = tid >> 6;
    int n = blockIdx.x * 64 + n_l;
    if (n < N) {
        #pragma unroll
        for (int r = 0; r < 8; r++) {
            int i0 = q * 32 + r * 4;
            float4 v = *(const float4*)&x[(size_t)n * FI + i0];
            xT[(i0 + 0) * 64 + n_l] = v.x;
            xT[(i0 + 1) * 64 + n_l] = v.y;
            xT[(i0 + 2) * 64 + n_l] = v.z;
            xT[(i0 + 3) * 64 + n_l] = v.w;
        }
    } else {
        #pragma unroll
        for (int r = 0; r < 8; r++) {
            int i0 = q * 32 + r * 4;
            xT[(i0 + 0) * 64 + n_l] = 0.f;
            xT[(i0 + 1) * 64 + n_l] = 0.f;
            xT[(i0 + 2) * 64 + n_l] = 0.f;
            xT[(i0 + 3) * 64 + n_l] = 0.f;
        }
    }
    __syncthreads();

    int ng = tid >> 4, jg = tid & 15, j0 = jg * 4;
    u64 al[8], ar[8];
    #pragma unroll
    for (int c = 0; c < 8; c++) { al[c] = 0; ar[c] = 0; }

    #pragma unroll 4
    for (int i = 0; i < FI; i++) {
        float4 xv = *(const float4*)&xT[i * 64 + ng * 4];
        const u64* pl = (const u64*)&wl[i * H + j0];
        const u64* pr = (const u64*)&wr[i * H + j0];
        u64 l0 = pl[0], l1 = pl[1], r0 = pr[0], r1 = pr[1];
        u64 x0 = pack2(xv.x, xv.x), x1 = pack2(xv.y, xv.y);
        u64 x2 = pack2(xv.z, xv.z), x3 = pack2(xv.w, xv.w);
        al[0] = ffma2(x0, l0, al[0]); al[1] = ffma2(x0, l1, al[1]);
        al[2] = ffma2(x1, l0, al[2]); al[3] = ffma2(x1, l1, al[3]);
        al[4] = ffma2(x2, l0, al[4]); al[5] = ffma2(x2, l1, al[5]);
        al[6] = ffma2(x3, l0, al[6]); al[7] = ffma2(x3, l1, al[7]);
        ar[0] = ffma2(x0, r0, ar[0]); ar[1] = ffma2(x0, r1, ar[1]);
        ar[2] = ffma2(x1, r0, ar[2]); ar[3] = ffma2(x1, r1, ar[3]);
        ar[4] = ffma2(x2, r0, ar[4]); ar[5] = ffma2(x2, r1, ar[5]);
        ar[6] = ffma2(x3, r0, ar[6]); ar[7] = ffma2(x3, r1, ar[7]);
    }

    float4 bb = *(const float4*)&bl[j0];
    int nb0 = blockIdx.x * 64 + ng * 4;
    #pragma unroll
    for (int c = 0; c < 4; c++) {
        int n2 = nb0 + c;
        if (n2 < N) {
            size_t o = (size_t)n2 * H + j0;
            float2 lo = unpack2(al[c * 2]), hi = unpack2(al[c * 2 + 1]);
            *(float4*)&g_xl[o] = make_float4(lo.x, lo.y, hi.x, hi.y);
            float2 ro = unpack2(ar[c * 2]), rh = unpack2(ar[c * 2 + 1]);
            *(float4*)&g_xb[o] = make_float4(ro.x + bb.x, ro.y + bb.y, rh.x + bb.z, rh.y + bb.w);
            *(float4*)&g_s[o] = make_float4(0.f, 0.f, 0.f, 0.f);
            if (jg == 0) g_cnt[n2] = 0.f;
        }
    }
}

// ------------------------------------------------- edge scatter
__global__ void k_scatter(const int* __restrict__ ei, int E, int do_cnt) {
    unsigned idx = blockIdx.x * 256u + threadIdx.x;
    unsigned e = idx >> 4;
    if (e >= (unsigned)E) return;
    int k4 = (int)(idx & 15u) * 4;
    int s = ei[e];
    int t = ei[(size_t)E + e];
    float4 v = *(const float4*)(g_xl + (size_t)s * H + k4);
    float* p = g_s + (size_t)t * H + k4;
    asm volatile("red.global.add.v4.f32 [%0], {%1,%2,%3,%4};"
                 :: "l"(p), "f"(v.x), "f"(v.y), "f"(v.z), "f"(v.w) : "memory");
    if (do_cnt && k4 == 0) atomicAdd(g_cnt + t, 1.0f);
}

// ------------------------------------------------- h0 = relu(s/cnt + xb); dual project Wl1/Wr1 (R8 form)
__global__ void __launch_bounds__(256) k_node_mid(const float* __restrict__ Wl,
                                                  const float* __restrict__ Wr,
                                                  const float* __restrict__ bl, int N) {
    extern __shared__ float sm[];
    float* hT = sm;                 // [64][64] 16KB
    float* wl = sm + H * 64;        // 16KB
    float* wr = wl + H * H;         // 16KB
    int tid = threadIdx.x;
    #pragma unroll
    for (int i = 0; i < 4; i++) {
        ((float4*)wl)[tid + i * 256] = ((const float4*)Wl)[tid + i * 256];
        ((float4*)wr)[tid + i * 256] = ((const float4*)Wr)[tid + i * 256];
    }
    {
        int n_l = tid >> 2, part = tid & 3, jp = part * 16;
        int n = blockIdx.x * 64 + n_l;
        if (n < N) {
            float inv = 1.0f / fmaxf(g_cnt[n], 1.0f);
            size_t o = (size_t)n * H + jp;
            #pragma unroll
            for (int c = 0; c < 4; c++) {
                float4 s4 = *(const float4*)&g_s[o + c * 4];
                float4 b4 = *(const float4*)&g_xb[o + c * 4];
                int jb = jp + c * 4;
                hT[(jb + 0) * 64 + n_l] = fmaxf(fmaf(s4.x, inv, b4.x), 0.f);
                hT[(jb + 1) * 64 + n_l] = fmaxf(fmaf(s4.y, inv, b4.y), 0.f);
                hT[(jb + 2) * 64 + n_l] = fmaxf(fmaf(s4.z, inv, b4.z), 0.f);
                hT[(jb + 3) * 64 + n_l] = fmaxf(fmaf(s4.w, inv, b4.w), 0.f);
                *(float4*)&g_s[o + c * 4] = make_float4(0.f, 0.f, 0.f, 0.f);
            }
        } else {
            #pragma unroll
            for (int c = 0; c < 16; c++) hT[(jp + c) * 64 + n_l] = 0.f;
        }
    }
    __syncthreads();

    int ng = tid >> 4, jg = tid & 15, j0 = jg * 4;
    u64 al[8], ar[8];
    #pragma unroll
    for (int c = 0; c < 8; c++) { al[c] = 0; ar[c] = 0; }

    #pragma unroll 4
    for (int k = 0; k < H; k++) {
        float4 xv = *(const float4*)&hT[k * 64 + ng * 4];
        const u64* pl = (const u64*)&wl[k * H + j0];
        const u64* pr = (const u64*)&wr[k * H + j0];
        u64 l0 = pl[0], l1 = pl[1], r0 = pr[0], r1 = pr[1];
        u64 x0 = pack2(xv.x, xv.x), x1 = pack2(xv.y, xv.y);
        u64 x2 = pack2(xv.z, xv.z), x3 = pack2(xv.w, xv.w);
        al[0] = ffma2(x0, l0, al[0]); al[1] = ffma2(x0, l1, al[1]);
        al[2] = ffma2(x1, l0, al[2]); al[3] = ffma2(x1, l1, al[3]);
        al[4] = ffma2(x2, l0, al[4]); al[5] = ffma2(x2, l1, al[5]);
        al[6] = ffma2(x3, l0, al[6]); al[7] = ffma2(x3, l1, al[7]);
        ar[0] = ffma2(x0, r0, ar[0]); ar[1] = ffma2(x0, r1, ar[1]);
        ar[2] = ffma2(x1, r0, ar[2]); ar[3] = ffma2(x1, r1, ar[3]);
        ar[4] = ffma2(x2, r0, ar[4]); ar[5] = ffma2(x2, r1, ar[5]);
        ar[6] = ffma2(x3, r0, ar[6]); ar[7] = ffma2(x3, r1, ar[7]);
    }

    float4 bb = *(const float4*)&bl[j0];
    int nb0 = blockIdx.x * 64 + ng * 4;
    #pragma unroll
    for (int c = 0; c < 4; c++) {
        int n2 = nb0 + c;
        if (n2 < N) {
            size_t o = (size_t)n2 * H + j0;
            float2 lo = unpack2(al[c * 2]), hi = unpack2(al[c * 2 + 1]);
            *(float4*)&g_xl[o] = make_float4(lo.x, lo.y, hi.x, hi.y);
            float2 ro = unpack2(ar[c * 2]), rh = unpack2(ar[c * 2 + 1]);
            *(float4*)&g_xb[o] = make_float4(ro.x + bb.x, ro.y + bb.y, rh.x + bb.z, rh.y + bb.w);
        }
    }
}

// ------------------------------------------------- h1 = relu(s/cnt + xb); g_hq = h1 @ Wo1 (R8 form)
__global__ void __launch_bounds__(256) k_node_fin(const float* __restrict__ Wo1, int N) {
    __shared__ float hT[H * 64];    // 16KB
    __shared__ float ws[H * H];     // 16KB
    int tid = threadIdx.x;
    #pragma unroll
    for (int i = 0; i < 4; i++)
        ((float4*)ws)[tid + i * 256] = ((const float4*)Wo1)[tid + i * 256];
    {
        int n_l = tid >> 2, part = tid & 3, jp = part * 16;
        int n = blockIdx.x * 64 + n_l;
        if (n < N) {
            float inv = 1.0f / fmaxf(g_cnt[n], 1.0f);
            size_t o = (size_t)n * H + jp;
            #pragma unroll
            for (int c = 0; c < 4; c++) {
                float4 s4 = *(const float4*)&g_s[o + c * 4];
                float4 b4 = *(const float4*)&g_xb[o + c * 4];
                int jb = jp + c * 4;
                hT[(jb + 0) * 64 + n_l] = fmaxf(fmaf(s4.x, inv, b4.x), 0.f);
                hT[(jb + 1) * 64 + n_l] = fmaxf(fmaf(s4.y, inv, b4.y), 0.f);
                hT[(jb + 2) * 64 + n_l] = fmaxf(fmaf(s4.z, inv, b4.z), 0.f);
                hT[(jb + 3) * 64 + n_l] = fmaxf(fmaf(s4.w, inv, b4.w), 0.f);
            }
        } else {
            #pragma unroll
            for (int c = 0; c < 16; c++) hT[(jp + c) * 64 + n_l] = 0.f;
        }
    }
    __syncthreads();

    int ng = tid >> 4, jg = tid & 15, j0 = jg * 4;
    u64 ac[8];
    #pragma unroll
    for (int c = 0; c < 8; c++) ac[c] = 0;

    #pragma unroll 4
    for (int k = 0; k < H; k++) {
        float4 xv = *(const float4*)&hT[k * 64 + ng * 4];
        const u64* pw = (const u64*)&ws[k * H + j0];
        u64 w0 = pw[0], w1 = pw[1];
        u64 x0 = pack2(xv.x, xv.x), x1 = pack2(xv.y, xv.y);
        u64 x2 = pack2(xv.z, xv.z), x3 = pack2(xv.w, xv.w);
        ac[0] = ffma2(x0, w0, ac[0]); ac[1] = ffma2(x0, w1, ac[1]);
        ac[2] = ffma2(x1, w0, ac[2]); ac[3] = ffma2(x1, w1, ac[3]);
        ac[4] = ffma2(x2, w0, ac[4]); ac[5] = ffma2(x2, w1, ac[5]);
        ac[6] = ffma2(x3, w0, ac[6]); ac[7] = ffma2(x3, w1, ac[7]);
    }

    int nb0 = blockIdx.x * 64 + ng * 4;
    #pragma unroll
    for (int c = 0; c < 4; c++) {
        int n2 = nb0 + c;
        if (n2 < N) {
            float2 lo = unpack2(ac[c * 2]), hi = unpack2(ac[c * 2 + 1]);
            *(float4*)&g_hq[(size_t)n2 * H + j0] = make_float4(lo.x, lo.y, hi.x, hi.y);
        }
    }
}

// ------------------------------------------------- per-edge head: block-tiled GEMM (R9 form)
// zs staged in smem; W2o streamed via LDG (tiny L1-resident table).
struct __align__(16) EdgeSmem {
    float zs[H][TE];        // 32 KB  (k-major)
    float we1t[H][16];      // 4 KB   ([k][i])
    float be1s[H];
    float b2os[H];
    float wo2s[H];
    int   sidx[TE];
    int   tidx[TE];
    float bo2s;
};

__global__ void __launch_bounds__(256) k_edge(const int* __restrict__ ei, int E,
                                              const float* __restrict__ edge_attr,
                                              const float* __restrict__ We1,
                                              const float* __restrict__ be1,
                                              const float* __restrict__ Wo2,
                                              const float* __restrict__ bo2,
                                              float* __restrict__ out) {
    __shared__ EdgeSmem S;
    int tid = threadIdx.x;
    long long e_base = (long long)blockIdx.x * TE;

    #pragma unroll
    for (int r = 0; r < 4; r++) {
        int idx = tid + r * 256;
        int kk = idx >> 4, ii = idx & 15;
        S.we1t[kk][ii] = We1[ii * H + kk];
    }
    if (tid < H) {
        S.be1s[tid] = be1[tid];
        S.b2os[tid] = g_b2o[tid];
        S.wo2s[tid] = Wo2[tid];
    }
    if (tid == 0) S.bo2s = bo2[0];
    if (tid < TE) {
        long long e = e_base + tid;
        S.sidx[tid] = (e < E) ? ei[e] : 0;
    } else {
        int el = tid - TE;
        long long e = e_base + el;
        S.tidx[el] = (e < E) ? ei[(size_t)E + e] : 0;
    }
    __syncthreads();

    // Phase A: zs[k][e] = relu(ea . We1[:,k] + be1[k]); 2 threads per edge
    {
        int th = tid >> 7;
        int el = tid & (TE - 1);
        long long e = e_base + el;
        float ea[16];
        if (e < E) {
            const float4* eap = (const float4*)(edge_attr + (size_t)e * 16);
            #pragma unroll
            for (int c = 0; c < 4; c++) {
                float4 v = eap[c];
                ea[4*c+0] = v.x; ea[4*c+1] = v.y; ea[4*c+2] = v.z; ea[4*c+3] = v.w;
            }
        } else {
            #pragma unroll
            for (int c = 0; c < 16; c++) ea[c] = 0.f;
        }
        int k0 = th * 32;
        #pragma unroll 4
        for (int k = k0; k < k0 + 32; k++) {
            float z = S.be1s[k];
            const float4* wp = (const float4*)S.we1t[k];
            #pragma unroll
            for (int q = 0; q < 4; q++) {
                float4 w = wp[q];
                z = fmaf(ea[4*q+0], w.x, z);
                z = fmaf(ea[4*q+1], w.y, z);
                z = fmaf(ea[4*q+2], w.z, z);
                z = fmaf(ea[4*q+3], w.w, z);
            }
            S.zs[k][el] = fmaxf(z, 0.f);
        }
    }
    __syncthreads();

    // Phase B: 4 edges x 8 j per thread; W2o streamed from global (L1-resident)
    int eg = tid >> 3;
    int jg = tid & 7;
    int e0 = eg * 4;
    int j0 = jg * 8;

    u64 acc2[16];
    #pragma unroll
    for (int i = 0; i < 4; i++) {
        int s = S.sidx[e0 + i];
        int t = S.tidx[e0 + i];
        const float4* ps = (const float4*)&g_hq[(size_t)s * H + j0];
        const float4* pt = (const float4*)&g_hq[(size_t)t * H + j0];
        float4 a0 = ps[0], a1 = ps[1], b0 = pt[0], b1 = pt[1];
        float4 c0 = *(const float4*)&S.b2os[j0];
        float4 c1 = *(const float4*)&S.b2os[j0 + 4];
        acc2[i*4+0] = pack2(a0.x + b0.x + c0.x, a0.y + b0.y + c0.y);
        acc2[i*4+1] = pack2(a0.z + b0.z + c0.z, a0.w + b0.w + c0.w);
        acc2[i*4+2] = pack2(a1.x + b1.x + c1.x, a1.y + b1.y + c1.y);
        acc2[i*4+3] = pack2(a1.z + b1.z + c1.z, a1.w + b1.w + c1.w);
    }

    #pragma unroll 4
    for (int k = 0; k < H; k++) {
        float4 zv = *(const float4*)&S.zs[k][e0];
        ulonglong2 wa = __ldg((const ulonglong2*)&g_W2o[k * H + j0]);
        ulonglong2 wb = __ldg((const ulonglong2*)&g_W2o[k * H + j0 + 4]);
        u64 w0 = wa.x, w1 = wa.y, w2 = wb.x, w3 = wb.y;
        u64 z0 = pack2(zv.x, zv.x), z1 = pack2(zv.y, zv.y);
        u64 z2 = pack2(zv.z, zv.z), z3 = pack2(zv.w, zv.w);
        acc2[0]  = ffma2(z0, w0, acc2[0]);  acc2[1]  = ffma2(z0, w1, acc2[1]);
        acc2[2]  = ffma2(z0, w2, acc2[2]);  acc2[3]  = ffma2(z0, w3, acc2[3]);
        acc2[4]  = ffma2(z1, w0, acc2[4]);  acc2[5]  = ffma2(z1, w1, acc2[5]);
        acc2[6]  = ffma2(z1, w2, acc2[6]);  acc2[7]  = ffma2(z1, w3, acc2[7]);
        acc2[8]  = ffma2(z2, w0, acc2[8]);  acc2[9]  = ffma2(z2, w1, acc2[9]);
        acc2[10] = ffma2(z2, w2, acc2[10]); acc2[11] = ffma2(z2, w3, acc2[11]);
        acc2[12] = ffma2(z3, w0, acc2[12]); acc2[13] = ffma2(z3, w1, acc2[13]);
        acc2[14] = ffma2(z3, w2, acc2[14]); acc2[15] = ffma2(z3, w3, acc2[15]);
    }

    float r[4];
    #pragma unroll
    for (int i = 0; i < 4; i++) {
        float po = 0.f;
        #pragma unroll
        for (int p = 0; p < 4; p++) {
            float2 a = unpack2(acc2[i*4+p]);
            po = fmaf(fmaxf(a.x, 0.f), S.wo2s[j0 + 2*p + 0], po);
            po = fmaf(fmaxf(a.y, 0.f), S.wo2s[j0 + 2*p + 1], po);
        }
        po += __shfl_xor_sync(0xffffffffu, po, 4);
        po += __shfl_xor_sync(0xffffffffu, po, 2);
        po += __shfl_xor_sync(0xffffffffu, po, 1);
        r[i] = po;
    }
    if (jg == 0) {
        float b = S.bo2s;
        #pragma unroll
        for (int i = 0; i < 4; i++)
            r[i] = 1.0f / (1.0f + expf(-(r[i] + b)));
        long long e = e_base + e0;
        if (e + 3 < E) {
            *(float4*)&out[e] = make_float4(r[0], r[1], r[2], r[3]);
        } else {
            #pragma unroll
            for (int i = 0; i < 4; i++)
                if (e + i < E) out[e + i] = r[i];
        }
    }
}

// ----------------------------------------------------------------------------
extern "C" void kernel_launch(void* const* d_in, const int* in_sizes, int n_in,
                              void* d_out, int out_size) {
    const float* x   = (const float*)d_in[0];
    const int*   ei  = (const int*)d_in[1];       // int32 (JAX x64 disabled)
    const float* eat = (const float*)d_in[2];
    const float* We1 = (const float*)d_in[3];
    const float* be1 = (const float*)d_in[4];
    const float* We2 = (const float*)d_in[5];
    const float* be2 = (const float*)d_in[6];
    const float* Wl0 = (const float*)d_in[7];
    const float* bl0 = (const float*)d_in[8];
    const float* Wr0 = (const float*)d_in[9];
    const float* Wl1 = (const float*)d_in[10];
    const float* bl1 = (const float*)d_in[11];
    const float* Wr1 = (const float*)d_in[12];
    const float* Wo1 = (const float*)d_in[13];
    const float* bo1 = (const float*)d_in[14];
    const float* Wo2 = (const float*)d_in[15];
    const float* bo2 = (const float*)d_in[16];

    int N = in_sizes[0] / FI;          // 100000
    if (N > NN) N = NN;
    int E = in_sizes[1] / 2;           // 1000000
    float* out = (float*)d_out;

    int nb64 = (N + 63) / 64;
    unsigned sth = (unsigned)E * 16u;
    unsigned sblocks = (sth + 255u) / 256u;

    int smem_dual = (FI * 64 + FI * H + FI * H) * 4;   // 96KB
    int smem_mid  = (H * 64 + H * H + H * H) * 4;      // 48KB
    cudaFuncSetAttribute(k_node_dual, cudaFuncAttributeMaxDynamicSharedMemorySize, smem_dual);
    cudaFuncSetAttribute(k_node_mid,  cudaFuncAttributeMaxDynamicSharedMemorySize, smem_mid);

    k_prep<<<H + 1, H>>>(We2, Wo1, be2, bo1);
    k_node_dual<<<nb64, 256, smem_dual>>>(x, Wl0, Wr0, bl0, N);
    k_scatter<<<sblocks, 256>>>(ei, E, 1);
    k_node_mid<<<nb64, 256, smem_mid>>>(Wl1, Wr1, bl1, N);
    k_scatter<<<sblocks, 256>>>(ei, E, 0);
    k_node_fin<<<nb64, 256>>>(Wo1, N);
    k_edge<<<(E + TE - 1) / TE, 256>>>(ei, E, eat, We1, be1, Wo2, bo2, out);
}

// round 11
// speedup vs baseline: 1.6157x; 1.6157x over previous
#include <cuda_runtime.h>
#include <cstdint>
#include <math.h>

#define NN 100000
#define FI 128
#define H  64
#define TE 128   // edges per block in k_edge

typedef unsigned long long u64;

__device__ __forceinline__ u64 ffma2(u64 a, u64 b, u64 c) {
    u64 d;
    asm("fma.rn.f32x2 %0, %1, %2, %3;" : "=l"(d) : "l"(a), "l"(b), "l"(c));
    return d;
}
__device__ __forceinline__ float2 unpack2(u64 p) {
    float2 f;
    asm("mov.b64 {%0,%1}, %2;" : "=f"(f.x), "=f"(f.y) : "l"(p));
    return f;
}
__device__ __forceinline__ u64 pack2(float lo, float hi) {
    u64 p;
    asm("mov.b64 %0, {%1,%2};" : "=l"(p) : "f"(lo), "f"(hi));
    return p;
}

// Scratch (device globals). 16B-aligned for float4 access.
__device__ __align__(16) float g_xl[(size_t)NN * H];
__device__ __align__(16) float g_xb[(size_t)NN * H];
__device__ __align__(16) float g_s [(size_t)NN * H];
__device__ __align__(16) float g_cnt[NN];
__device__ __align__(16) float g_hq[(size_t)NN * H];
__device__ __align__(16) float g_W2o[H * H];
__device__ __align__(16) float g_b2o[H];

// ---------------------------------------------------------------- prep (parallel)
__global__ void k_prep(const float* __restrict__ We2, const float* __restrict__ Wo1,
                       const float* __restrict__ be2, const float* __restrict__ bo1) {
    int j = threadIdx.x;
    int b = blockIdx.x;
    if (b < H) {
        float acc = 0.f;
        #pragma unroll 8
        for (int k = 0; k < H; k++) acc += We2[b * H + k] * Wo1[k * H + j];
        g_W2o[b * H + j] = acc;
    } else {
        float acc = bo1[j];
        #pragma unroll 8
        for (int k = 0; k < H; k++) acc += be2[k] * Wo1[k * H + j];
        g_b2o[j] = acc;
    }
}

// ------------------------------------------------- fused node linear: xl = x@Wl, xb = x@Wr + bl
// 64 nodes/block, 256 threads; thread = 4 nodes x 4 j; x staged transposed.
__global__ void __launch_bounds__(256) k_node_dual(const float* __restrict__ x,
                                                   const float* __restrict__ Wl,
                                                   const float* __restrict__ Wr,
                                                   const float* __restrict__ bl, int N) {
    extern __shared__ float sm[];
    float* xT = sm;                 // [128][64]  32KB
    float* wl = sm + FI * 64;       // [128][64]  32KB
    float* wr = wl + FI * H;        // [128][64]  32KB
    int tid = threadIdx.x;
    #pragma unroll
    for (int i = 0; i < 8; i++) {
        ((float4*)wl)[tid + i * 256] = ((const float4*)Wl)[tid + i * 256];
        ((float4*)wr)[tid + i * 256] = ((const float4*)Wr)[tid + i * 256];
    }
    int n_l = tid & 63, q = tid >> 6;
    int n = blockIdx.x * 64 + n_l;
    if (n < N) {
        #pragma unroll
        for (int r = 0; r < 8; r++) {
            int i0 = q * 32 + r * 4;
            float4 v = *(const float4*)&x[(size_t)n * FI + i0];
            xT[(i0 + 0) * 64 + n_l] = v.x;
            xT[(i0 + 1) * 64 + n_l] = v.y;
            xT[(i0 + 2) * 64 + n_l] = v.z;
            xT[(i0 + 3) * 64 + n_l] = v.w;
        }
    } else {
        #pragma unroll
        for (int r = 0; r < 8; r++) {
            int i0 = q * 32 + r * 4;
            xT[(i0 + 0) * 64 + n_l] = 0.f;
            xT[(i0 + 1) * 64 + n_l] = 0.f;
            xT[(i0 + 2) * 64 + n_l] = 0.f;
            xT[(i0 + 3) * 64 + n_l] = 0.f;
        }
    }
    __syncthreads();

    int ng = tid >> 4, jg = tid & 15, j0 = jg * 4;
    u64 al[8], ar[8];
    #pragma unroll
    for (int c = 0; c < 8; c++) { al[c] = 0; ar[c] = 0; }

    #pragma unroll 4
    for (int i = 0; i < FI; i++) {
        float4 xv = *(const float4*)&xT[i * 64 + ng * 4];
        const u64* pl = (const u64*)&wl[i * H + j0];
        const u64* pr = (const u64*)&wr[i * H + j0];
        u64 l0 = pl[0], l1 = pl[1], r0 = pr[0], r1 = pr[1];
        u64 x0 = pack2(xv.x, xv.x), x1 = pack2(xv.y, xv.y);
        u64 x2 = pack2(xv.z, xv.z), x3 = pack2(xv.w, xv.w);
        al[0] = ffma2(x0, l0, al[0]); al[1] = ffma2(x0, l1, al[1]);
        al[2] = ffma2(x1, l0, al[2]); al[3] = ffma2(x1, l1, al[3]);
        al[4] = ffma2(x2, l0, al[4]); al[5] = ffma2(x2, l1, al[5]);
        al[6] = ffma2(x3, l0, al[6]); al[7] = ffma2(x3, l1, al[7]);
        ar[0] = ffma2(x0, r0, ar[0]); ar[1] = ffma2(x0, r1, ar[1]);
        ar[2] = ffma2(x1, r0, ar[2]); ar[3] = ffma2(x1, r1, ar[3]);
        ar[4] = ffma2(x2, r0, ar[4]); ar[5] = ffma2(x2, r1, ar[5]);
        ar[6] = ffma2(x3, r0, ar[6]); ar[7] = ffma2(x3, r1, ar[7]);
    }

    float4 bb = *(const float4*)&bl[j0];
    int nb0 = blockIdx.x * 64 + ng * 4;
    #pragma unroll
    for (int c = 0; c < 4; c++) {
        int n2 = nb0 + c;
        if (n2 < N) {
            size_t o = (size_t)n2 * H + j0;
            float2 lo = unpack2(al[c * 2]), hi = unpack2(al[c * 2 + 1]);
            *(float4*)&g_xl[o] = make_float4(lo.x, lo.y, hi.x, hi.y);
            float2 ro = unpack2(ar[c * 2]), rh = unpack2(ar[c * 2 + 1]);
            *(float4*)&g_xb[o] = make_float4(ro.x + bb.x, ro.y + bb.y, rh.x + bb.z, rh.y + bb.w);
            *(float4*)&g_s[o] = make_float4(0.f, 0.f, 0.f, 0.f);
            if (jg == 0) g_cnt[n2] = 0.f;
        }
    }
}

// ------------------------------------------------- edge scatter
__global__ void k_scatter(const int* __restrict__ ei, int E, int do_cnt) {
    unsigned idx = blockIdx.x * 256u + threadIdx.x;
    unsigned e = idx >> 4;
    if (e >= (unsigned)E) return;
    int k4 = (int)(idx & 15u) * 4;
    int s = ei[e];
    int t = ei[(size_t)E + e];
    float4 v = *(const float4*)(g_xl + (size_t)s * H + k4);
    float* p = g_s + (size_t)t * H + k4;
    asm volatile("red.global.add.v4.f32 [%0], {%1,%2,%3,%4};"
                 :: "l"(p), "f"(v.x), "f"(v.y), "f"(v.z), "f"(v.w) : "memory");
    if (do_cnt && k4 == 0) atomicAdd(g_cnt + t, 1.0f);
}

// ------------------------------------------------- h0 = relu(s/cnt + xb); dual project Wl1/Wr1
__global__ void __launch_bounds__(256) k_node_mid(const float* __restrict__ Wl,
                                                  const float* __restrict__ Wr,
                                                  const float* __restrict__ bl, int N) {
    extern __shared__ float sm[];
    float* hT = sm;                 // [64][64] 16KB
    float* wl = sm + H * 64;        // 16KB
    float* wr = wl + H * H;         // 16KB
    int tid = threadIdx.x;
    #pragma unroll
    for (int i = 0; i < 4; i++) {
        ((float4*)wl)[tid + i * 256] = ((const float4*)Wl)[tid + i * 256];
        ((float4*)wr)[tid + i * 256] = ((const float4*)Wr)[tid + i * 256];
    }
    {
        int n_l = tid >> 2, part = tid & 3, jp = part * 16;
        int n = blockIdx.x * 64 + n_l;
        if (n < N) {
            float inv = 1.0f / fmaxf(g_cnt[n], 1.0f);
            size_t o = (size_t)n * H + jp;
            #pragma unroll
            for (int c = 0; c < 4; c++) {
                float4 s4 = *(const float4*)&g_s[o + c * 4];
                float4 b4 = *(const float4*)&g_xb[o + c * 4];
                int jb = jp + c * 4;
                hT[(jb + 0) * 64 + n_l] = fmaxf(fmaf(s4.x, inv, b4.x), 0.f);
                hT[(jb + 1) * 64 + n_l] = fmaxf(fmaf(s4.y, inv, b4.y), 0.f);
                hT[(jb + 2) * 64 + n_l] = fmaxf(fmaf(s4.z, inv, b4.z), 0.f);
                hT[(jb + 3) * 64 + n_l] = fmaxf(fmaf(s4.w, inv, b4.w), 0.f);
                *(float4*)&g_s[o + c * 4] = make_float4(0.f, 0.f, 0.f, 0.f);
            }
        } else {
            #pragma unroll
            for (int c = 0; c < 16; c++) hT[(jp + c) * 64 + n_l] = 0.f;
        }
    }
    __syncthreads();

    int ng = tid >> 4, jg = tid & 15, j0 = jg * 4;
    u64 al[8], ar[8];
    #pragma unroll
    for (int c = 0; c < 8; c++) { al[c] = 0; ar[c] = 0; }

    #pragma unroll 4
    for (int k = 0; k < H; k++) {
        float4 xv = *(const float4*)&hT[k * 64 + ng * 4];
        const u64* pl = (const u64*)&wl[k * H + j0];
        const u64* pr = (const u64*)&wr[k * H + j0];
        u64 l0 = pl[0], l1 = pl[1], r0 = pr[0], r1 = pr[1];
        u64 x0 = pack2(xv.x, xv.x), x1 = pack2(xv.y, xv.y);
        u64 x2 = pack2(xv.z, xv.z), x3 = pack2(xv.w, xv.w);
        al[0] = ffma2(x0, l0, al[0]); al[1] = ffma2(x0, l1, al[1]);
        al[2] = ffma2(x1, l0, al[2]); al[3] = ffma2(x1, l1, al[3]);
        al[4] = ffma2(x2, l0, al[4]); al[5] = ffma2(x2, l1, al[5]);
        al[6] = ffma2(x3, l0, al[6]); al[7] = ffma2(x3, l1, al[7]);
        ar[0] = ffma2(x0, r0, ar[0]); ar[1] = ffma2(x0, r1, ar[1]);
        ar[2] = ffma2(x1, r0, ar[2]); ar[3] = ffma2(x1, r1, ar[3]);
        ar[4] = ffma2(x2, r0, ar[4]); ar[5] = ffma2(x2, r1, ar[5]);
        ar[6] = ffma2(x3, r0, ar[6]); ar[7] = ffma2(x3, r1, ar[7]);
    }

    float4 bb = *(const float4*)&bl[j0];
    int nb0 = blockIdx.x * 64 + ng * 4;
    #pragma unroll
    for (int c = 0; c < 4; c++) {
        int n2 = nb0 + c;
        if (n2 < N) {
            size_t o = (size_t)n2 * H + j0;
            float2 lo = unpack2(al[c * 2]), hi = unpack2(al[c * 2 + 1]);
            *(float4*)&g_xl[o] = make_float4(lo.x, lo.y, hi.x, hi.y);
            float2 ro = unpack2(ar[c * 2]), rh = unpack2(ar[c * 2 + 1]);
            *(float4*)&g_xb[o] = make_float4(ro.x + bb.x, ro.y + bb.y, rh.x + bb.z, rh.y + bb.w);
        }
    }
}

// ------------------------------------------------- h1 = relu(s/cnt + xb); g_hq = h1 @ Wo1
__global__ void __launch_bounds__(256) k_node_fin(const float* __restrict__ Wo1, int N) {
    __shared__ float hT[H * 64];    // 16KB
    __shared__ float ws[H * H];     // 16KB
    int tid = threadIdx.x;
    #pragma unroll
    for (int i = 0; i < 4; i++)
        ((float4*)ws)[tid + i * 256] = ((const float4*)Wo1)[tid + i * 256];
    {
        int n_l = tid >> 2, part = tid & 3, jp = part * 16;
        int n = blockIdx.x * 64 + n_l;
        if (n < N) {
            float inv = 1.0f / fmaxf(g_cnt[n], 1.0f);
            size_t o = (size_t)n * H + jp;
            #pragma unroll
            for (int c = 0; c < 4; c++) {
                float4 s4 = *(const float4*)&g_s[o + c * 4];
                float4 b4 = *(const float4*)&g_xb[o + c * 4];
                int jb = jp + c * 4;
                hT[(jb + 0) * 64 + n_l] = fmaxf(fmaf(s4.x, inv, b4.x), 0.f);
                hT[(jb + 1) * 64 + n_l] = fmaxf(fmaf(s4.y, inv, b4.y), 0.f);
                hT[(jb + 2) * 64 + n_l] = fmaxf(fmaf(s4.z, inv, b4.z), 0.f);
                hT[(jb + 3) * 64 + n_l] = fmaxf(fmaf(s4.w, inv, b4.w), 0.f);
            }
        } else {
            #pragma unroll
            for (int c = 0; c < 16; c++) hT[(jp + c) * 64 + n_l] = 0.f;
        }
    }
    __syncthreads();

    int ng = tid >> 4, jg = tid & 15, j0 = jg * 4;
    u64 ac[8];
    #pragma unroll
    for (int c = 0; c < 8; c++) ac[c] = 0;

    #pragma unroll 4
    for (int k = 0; k < H; k++) {
        float4 xv = *(const float4*)&hT[k * 64 + ng * 4];
        const u64* pw = (const u64*)&ws[k * H + j0];
        u64 w0 = pw[0], w1 = pw[1];
        u64 x0 = pack2(xv.x, xv.x), x1 = pack2(xv.y, xv.y);
        u64 x2 = pack2(xv.z, xv.z), x3 = pack2(xv.w, xv.w);
        ac[0] = ffma2(x0, w0, ac[0]); ac[1] = ffma2(x0, w1, ac[1]);
        ac[2] = ffma2(x1, w0, ac[2]); ac[3] = ffma2(x1, w1, ac[3]);
        ac[4] = ffma2(x2, w0, ac[4]); ac[5] = ffma2(x2, w1, ac[5]);
        ac[6] = ffma2(x3, w0, ac[6]); ac[7] = ffma2(x3, w1, ac[7]);
    }

    int nb0 = blockIdx.x * 64 + ng * 4;
    #pragma unroll
    for (int c = 0; c < 4; c++) {
        int n2 = nb0 + c;
        if (n2 < N) {
            float2 lo = unpack2(ac[c * 2]), hi = unpack2(ac[c * 2 + 1]);
            *(float4*)&g_hq[(size_t)n2 * H + j0] = make_float4(lo.x, lo.y, hi.x, hi.y);
        }
    }
}

// ------------------------------------------------- per-edge head: block-tiled GEMM
// 128 edges/block, 256 threads. Phase A: z[k][e]=relu(ea.We1+be1) into smem.
// Phase B: thread owns 4 edges x 8 j; 3 LDS feed 16 ffma2 per k-step.
struct __align__(16) EdgeSmem {
    float zs[H][TE];
    float w2os[H][H];
    float we1t[H][16];
    float be1s[H];
    float b2os[H];
    float wo2s[H];
    int   sidx[TE];
    int   tidx[TE];
    float bo2s;
};

__global__ void __launch_bounds__(256) k_edge(const int* __restrict__ ei, int E,
                                              const float* __restrict__ edge_attr,
                                              const float* __restrict__ We1,
                                              const float* __restrict__ be1,
                                              const float* __restrict__ Wo2,
                                              const float* __restrict__ bo2,
                                              float* __restrict__ out) {
    extern __shared__ char smem_raw[];
    EdgeSmem* S = (EdgeSmem*)smem_raw;
    int tid = threadIdx.x;
    long long e_base = (long long)blockIdx.x * TE;

    #pragma unroll
    for (int i = 0; i < (H * H / 4) / 256; i++)
        ((float4*)S->w2os)[tid + i * 256] = ((const float4*)g_W2o)[tid + i * 256];
    #pragma unroll
    for (int r = 0; r < 4; r++) {
        int idx = tid + r * 256;
        int kk = idx >> 4, ii = idx & 15;
        S->we1t[kk][ii] = We1[ii * H + kk];
    }
    if (tid < H) {
        S->be1s[tid] = be1[tid];
        S->b2os[tid] = g_b2o[tid];
        S->wo2s[tid] = Wo2[tid];
    }
    if (tid == 0) S->bo2s = bo2[0];
    if (tid < TE) {
        long long e = e_base + tid;
        S->sidx[tid] = (e < E) ? ei[e] : 0;
    } else {
        int el = tid - TE;
        long long e = e_base + el;
        S->tidx[el] = (e < E) ? ei[(size_t)E + e] : 0;
    }
    __syncthreads();

    {
        int th = tid >> 7;
        int el = tid & (TE - 1);
        long long e = e_base + el;
        float ea[16];
        if (e < E) {
            const float4* eap = (const float4*)(edge_attr + (size_t)e * 16);
            #pragma unroll
            for (int c = 0; c < 4; c++) {
                float4 v = eap[c];
                ea[4*c+0] = v.x; ea[4*c+1] = v.y; ea[4*c+2] = v.z; ea[4*c+3] = v.w;
            }
        } else {
            #pragma unroll
            for (int c = 0; c < 16; c++) ea[c] = 0.f;
        }
        int k0 = th * 32;
        #pragma unroll 4
        for (int k = k0; k < k0 + 32; k++) {
            float z = S->be1s[k];
            const float4* wp = (const float4*)S->we1t[k];
            #pragma unroll
            for (int q = 0; q < 4; q++) {
                float4 w = wp[q];
                z = fmaf(ea[4*q+0], w.x, z);
                z = fmaf(ea[4*q+1], w.y, z);
                z = fmaf(ea[4*q+2], w.z, z);
                z = fmaf(ea[4*q+3], w.w, z);
            }
            S->zs[k][el] = fmaxf(z, 0.f);
        }
    }
    __syncthreads();

    int eg = tid >> 3;
    int jg = tid & 7;
    int e0 = eg * 4;
    int j0 = jg * 8;

    u64 acc2[16];
    #pragma unroll
    for (int i = 0; i < 4; i++) {
        int s = S->sidx[e0 + i];
        int t = S->tidx[e0 + i];
        const float4* ps = (const float4*)&g_hq[(size_t)s * H + j0];
        const float4* pt = (const float4*)&g_hq[(size_t)t * H + j0];
        float4 a0 = ps[0], a1 = ps[1], b0 = pt[0], b1 = pt[1];
        float4 c0 = *(const float4*)&S->b2os[j0];
        float4 c1 = *(const float4*)&S->b2os[j0 + 4];
        acc2[i*4+0] = pack2(a0.x + b0.x + c0.x, a0.y + b0.y + c0.y);
        acc2[i*4+1] = pack2(a0.z + b0.z + c0.z, a0.w + b0.w + c0.w);
        acc2[i*4+2] = pack2(a1.x + b1.x + c1.x, a1.y + b1.y + c1.y);
        acc2[i*4+3] = pack2(a1.z + b1.z + c1.z, a1.w + b1.w + c1.w);
    }

    #pragma unroll 2
    for (int k = 0; k < H; k++) {
        float4 zv = *(const float4*)&S->zs[k][e0];
        const u64* wp = (const u64*)&S->w2os[k][j0];
        u64 w0 = wp[0], w1 = wp[1], w2 = wp[2], w3 = wp[3];
        u64 z0 = pack2(zv.x, zv.x), z1 = pack2(zv.y, zv.y);
        u64 z2 = pack2(zv.z, zv.z), z3 = pack2(zv.w, zv.w);
        acc2[0]  = ffma2(z0, w0, acc2[0]);  acc2[1]  = ffma2(z0, w1, acc2[1]);
        acc2[2]  = ffma2(z0, w2, acc2[2]);  acc2[3]  = ffma2(z0, w3, acc2[3]);
        acc2[4]  = ffma2(z1, w0, acc2[4]);  acc2[5]  = ffma2(z1, w1, acc2[5]);
        acc2[6]  = ffma2(z1, w2, acc2[6]);  acc2[7]  = ffma2(z1, w3, acc2[7]);
        acc2[8]  = ffma2(z2, w0, acc2[8]);  acc2[9]  = ffma2(z2, w1, acc2[9]);
        acc2[10] = ffma2(z2, w2, acc2[10]); acc2[11] = ffma2(z2, w3, acc2[11]);
        acc2[12] = ffma2(z3, w0, acc2[12]); acc2[13] = ffma2(z3, w1, acc2[13]);
        acc2[14] = ffma2(z3, w2, acc2[14]); acc2[15] = ffma2(z3, w3, acc2[15]);
    }

    float r[4];
    #pragma unroll
    for (int i = 0; i < 4; i++) {
        float po = 0.f;
        #pragma unroll
        for (int p = 0; p < 4; p++) {
            float2 a = unpack2(acc2[i*4+p]);
            po = fmaf(fmaxf(a.x, 0.f), S->wo2s[j0 + 2*p + 0], po);
            po = fmaf(fmaxf(a.y, 0.f), S->wo2s[j0 + 2*p + 1], po);
        }
        po += __shfl_xor_sync(0xffffffffu, po, 4);
        po += __shfl_xor_sync(0xffffffffu, po, 2);
        po += __shfl_xor_sync(0xffffffffu, po, 1);
        r[i] = po;
    }
    if (jg == 0) {
        float b = S->bo2s;
        #pragma unroll
        for (int i = 0; i < 4; i++)
            r[i] = 1.0f / (1.0f + expf(-(r[i] + b)));
        long long e = e_base + e0;
        if (e + 3 < E) {
            *(float4*)&out[e] = make_float4(r[0], r[1], r[2], r[3]);
        } else {
            #pragma unroll
            for (int i = 0; i < 4; i++)
                if (e + i < E) out[e + i] = r[i];
        }
    }
}

// ----------------------------------------------------------------------------
extern "C" void kernel_launch(void* const* d_in, const int* in_sizes, int n_in,
                              void* d_out, int out_size) {
    const float* x   = (const float*)d_in[0];
    const int*   ei  = (const int*)d_in[1];       // int32 (JAX x64 disabled)
    const float* eat = (const float*)d_in[2];
    const float* We1 = (const float*)d_in[3];
    const float* be1 = (const float*)d_in[4];
    const float* We2 = (const float*)d_in[5];
    const float* be2 = (const float*)d_in[6];
    const float* Wl0 = (const float*)d_in[7];
    const float* bl0 = (const float*)d_in[8];
    const float* Wr0 = (const float*)d_in[9];
    const float* Wl1 = (const float*)d_in[10];
    const float* bl1 = (const float*)d_in[11];
    const float* Wr1 = (const float*)d_in[12];
    const float* Wo1 = (const float*)d_in[13];
    const float* bo1 = (const float*)d_in[14];
    const float* Wo2 = (const float*)d_in[15];
    const float* bo2 = (const float*)d_in[16];

    int N = in_sizes[0] / FI;          // 100000
    if (N > NN) N = NN;
    int E = in_sizes[1] / 2;           // 1000000
    float* out = (float*)d_out;

    int nb64 = (N + 63) / 64;
    unsigned sth = (unsigned)E * 16u;
    unsigned sblocks = (sth + 255u) / 256u;

    int smem_dual = (FI * 64 + FI * H + FI * H) * 4;   // 96KB
    int smem_mid  = (H * 64 + H * H + H * H) * 4;      // 48KB
    int smem_edge = (int)sizeof(EdgeSmem);
    cudaFuncSetAttribute(k_node_dual, cudaFuncAttributeMaxDynamicSharedMemorySize, smem_dual);
    cudaFuncSetAttribute(k_node_mid,  cudaFuncAttributeMaxDynamicSharedMemorySize, smem_mid);
    cudaFuncSetAttribute(k_edge,      cudaFuncAttributeMaxDynamicSharedMemorySize, smem_edge);

    k_prep<<<H + 1, H>>>(We2, Wo1, be2, bo1);
    k_node_dual<<<nb64, 256, smem_dual>>>(x, Wl0, Wr0, bl0, N);
    k_scatter<<<sblocks, 256>>>(ei, E, 1);
    k_node_mid<<<nb64, 256, smem_mid>>>(Wl1, Wr1, bl1, N);
    k_scatter<<<sblocks, 256>>>(ei, E, 0);
    k_node_fin<<<nb64, 256>>>(Wo1, N);
    k_edge<<<(E + TE - 1) / TE, 256, smem_edge>>>(ei, E, eat, We1, be1, Wo2, bo2, out);
}

// round 15
// speedup vs baseline: 1.6167x; 1.0006x over previous
#include <cuda_runtime.h>
#include <cstdint>
#include <math.h>

#define NN 100000
#define FI 128
#define H  64
#define TE 128   // edges per block in k_edge

typedef unsigned long long u64;

__device__ __forceinline__ u64 ffma2(u64 a, u64 b, u64 c) {
    u64 d;
    asm("fma.rn.f32x2 %0, %1, %2, %3;" : "=l"(d) : "l"(a), "l"(b), "l"(c));
    return d;
}
__device__ __forceinline__ float2 unpack2(u64 p) {
    float2 f;
    asm("mov.b64 {%0,%1}, %2;" : "=f"(f.x), "=f"(f.y) : "l"(p));
    return f;
}
__device__ __forceinline__ u64 pack2(float lo, float hi) {
    u64 p;
    asm("mov.b64 %0, {%1,%2};" : "=l"(p) : "f"(lo), "f"(hi));
    return p;
}

// Scratch (device globals). 16B-aligned for float4 access.
__device__ __align__(16) float g_xl[(size_t)NN * H];
__device__ __align__(16) float g_xb[(size_t)NN * H];
__device__ __align__(16) float g_s [(size_t)NN * H];
__device__ __align__(16) float g_cnt[NN];
__device__ __align__(16) float g_hq[(size_t)NN * H];
__device__ __align__(16) float g_W2o[H * H];
__device__ __align__(16) float g_b2o[H];

// ---------------------------------------------------------------- prep (parallel)
__global__ void k_prep(const float* __restrict__ We2, const float* __restrict__ Wo1,
                       const float* __restrict__ be2, const float* __restrict__ bo1) {
    int j = threadIdx.x;
    int b = blockIdx.x;
    if (b < H) {
        float acc = 0.f;
        #pragma unroll 8
        for (int k = 0; k < H; k++) acc += We2[b * H + k] * Wo1[k * H + j];
        g_W2o[b * H + j] = acc;
    } else {
        float acc = bo1[j];
        #pragma unroll 8
        for (int k = 0; k < H; k++) acc += be2[k] * Wo1[k * H + j];
        g_b2o[j] = acc;
    }
}

// ------------------------------------------------- fused node linear: xl = x@Wl, xb = x@Wr + bl
// 64 nodes/block, 256 threads; thread = 4 nodes x 4 j.
// i-dimension processed in 2 chunks of 64 so smem = 48KB -> 4 blocks/SM (was 96KB/2 blocks).
__global__ void __launch_bounds__(256) k_node_dual(const float* __restrict__ x,
                                                   const float* __restrict__ Wl,
                                                   const float* __restrict__ Wr,
                                                   const float* __restrict__ bl, int N) {
    __shared__ float xT[64 * 64];   // 16KB  [i_local][n]
    __shared__ float wl[64 * H];    // 16KB
    __shared__ float wr[64 * H];    // 16KB   total 48KB
    int tid = threadIdx.x;
    int ng = tid >> 4, jg = tid & 15, j0 = jg * 4;
    int nbase = blockIdx.x * 64;

    u64 al[8], ar[8];
    #pragma unroll
    for (int c = 0; c < 8; c++) { al[c] = 0; ar[c] = 0; }

    #pragma unroll
    for (int ch = 0; ch < 2; ch++) {
        __syncthreads();   // previous chunk's reads done before overwrite (no-op first iter)
        // weights chunk: 64 rows x 64 cols = 1024 float4
        #pragma unroll
        for (int i = 0; i < 4; i++) {
            ((float4*)wl)[tid + i * 256] = ((const float4*)(Wl + ch * 64 * H))[tid + i * 256];
            ((float4*)wr)[tid + i * 256] = ((const float4*)(Wr + ch * 64 * H))[tid + i * 256];
        }
        // x chunk transposed
        {
            int n_l = tid & 63, q = tid >> 6;     // q in 0..3 -> i range q*16..q*16+15
            int n = nbase + n_l;
            #pragma unroll
            for (int r = 0; r < 4; r++) {
                int i0 = q * 16 + r * 4;
                float4 v = make_float4(0.f, 0.f, 0.f, 0.f);
                if (n < N) v = *(const float4*)&x[(size_t)n * FI + ch * 64 + i0];
                xT[(i0 + 0) * 64 + n_l] = v.x;
                xT[(i0 + 1) * 64 + n_l] = v.y;
                xT[(i0 + 2) * 64 + n_l] = v.z;
                xT[(i0 + 3) * 64 + n_l] = v.w;
            }
        }
        __syncthreads();

        #pragma unroll 4
        for (int i = 0; i < 64; i++) {
            float4 xv = *(const float4*)&xT[i * 64 + ng * 4];
            const u64* pl = (const u64*)&wl[i * H + j0];
            const u64* pr = (const u64*)&wr[i * H + j0];
            u64 l0 = pl[0], l1 = pl[1], r0 = pr[0], r1 = pr[1];
            u64 x0 = pack2(xv.x, xv.x), x1 = pack2(xv.y, xv.y);
            u64 x2 = pack2(xv.z, xv.z), x3 = pack2(xv.w, xv.w);
            al[0] = ffma2(x0, l0, al[0]); al[1] = ffma2(x0, l1, al[1]);
            al[2] = ffma2(x1, l0, al[2]); al[3] = ffma2(x1, l1, al[3]);
            al[4] = ffma2(x2, l0, al[4]); al[5] = ffma2(x2, l1, al[5]);
            al[6] = ffma2(x3, l0, al[6]); al[7] = ffma2(x3, l1, al[7]);
            ar[0] = ffma2(x0, r0, ar[0]); ar[1] = ffma2(x0, r1, ar[1]);
            ar[2] = ffma2(x1, r0, ar[2]); ar[3] = ffma2(x1, r1, ar[3]);
            ar[4] = ffma2(x2, r0, ar[4]); ar[5] = ffma2(x2, r1, ar[5]);
            ar[6] = ffma2(x3, r0, ar[6]); ar[7] = ffma2(x3, r1, ar[7]);
        }
    }

    float4 bb = *(const float4*)&bl[j0];
    int nb0 = nbase + ng * 4;
    #pragma unroll
    for (int c = 0; c < 4; c++) {
        int n2 = nb0 + c;
        if (n2 < N) {
            size_t o = (size_t)n2 * H + j0;
            float2 lo = unpack2(al[c * 2]), hi = unpack2(al[c * 2 + 1]);
            *(float4*)&g_xl[o] = make_float4(lo.x, lo.y, hi.x, hi.y);
            float2 ro = unpack2(ar[c * 2]), rh = unpack2(ar[c * 2 + 1]);
            *(float4*)&g_xb[o] = make_float4(ro.x + bb.x, ro.y + bb.y, rh.x + bb.z, rh.y + bb.w);
            *(float4*)&g_s[o] = make_float4(0.f, 0.f, 0.f, 0.f);
            if (jg == 0) g_cnt[n2] = 0.f;
        }
    }
}

// ------------------------------------------------- edge scatter
__global__ void k_scatter(const int* __restrict__ ei, int E, int do_cnt) {
    unsigned idx = blockIdx.x * 256u + threadIdx.x;
    unsigned e = idx >> 4;
    if (e >= (unsigned)E) return;
    int k4 = (int)(idx & 15u) * 4;
    int s = ei[e];
    int t = ei[(size_t)E + e];
    float4 v = *(const float4*)(g_xl + (size_t)s * H + k4);
    float* p = g_s + (size_t)t * H + k4;
    asm volatile("red.global.add.v4.f32 [%0], {%1,%2,%3,%4};"
                 :: "l"(p), "f"(v.x), "f"(v.y), "f"(v.z), "f"(v.w) : "memory");
    if (do_cnt && k4 == 0) atomicAdd(g_cnt + t, 1.0f);
}

// ------------------------------------------------- h0 = relu(s/cnt + xb); dual project Wl1/Wr1
__global__ void __launch_bounds__(256) k_node_mid(const float* __restrict__ Wl,
                                                  const float* __restrict__ Wr,
                                                  const float* __restrict__ bl, int N) {
    extern __shared__ float sm[];
    float* hT = sm;                 // [64][64] 16KB
    float* wl = sm + H * 64;        // 16KB
    float* wr = wl + H * H;         // 16KB
    int tid = threadIdx.x;
    #pragma unroll
    for (int i = 0; i < 4; i++) {
        ((float4*)wl)[tid + i * 256] = ((const float4*)Wl)[tid + i * 256];
        ((float4*)wr)[tid + i * 256] = ((const float4*)Wr)[tid + i * 256];
    }
    {
        int n_l = tid >> 2, part = tid & 3, jp = part * 16;
        int n = blockIdx.x * 64 + n_l;
        if (n < N) {
            float inv = 1.0f / fmaxf(g_cnt[n], 1.0f);
            size_t o = (size_t)n * H + jp;
            #pragma unroll
            for (int c = 0; c < 4; c++) {
                float4 s4 = *(const float4*)&g_s[o + c * 4];
                float4 b4 = *(const float4*)&g_xb[o + c * 4];
                int jb = jp + c * 4;
                hT[(jb + 0) * 64 + n_l] = fmaxf(fmaf(s4.x, inv, b4.x), 0.f);
                hT[(jb + 1) * 64 + n_l] = fmaxf(fmaf(s4.y, inv, b4.y), 0.f);
                hT[(jb + 2) * 64 + n_l] = fmaxf(fmaf(s4.z, inv, b4.z), 0.f);
                hT[(jb + 3) * 64 + n_l] = fmaxf(fmaf(s4.w, inv, b4.w), 0.f);
                *(float4*)&g_s[o + c * 4] = make_float4(0.f, 0.f, 0.f, 0.f);
            }
        } else {
            #pragma unroll
            for (int c = 0; c < 16; c++) hT[(jp + c) * 64 + n_l] = 0.f;
        }
    }
    __syncthreads();

    int ng = tid >> 4, jg = tid & 15, j0 = jg * 4;
    u64 al[8], ar[8];
    #pragma unroll
    for (int c = 0; c < 8; c++) { al[c] = 0; ar[c] = 0; }

    #pragma unroll 4
    for (int k = 0; k < H; k++) {
        float4 xv = *(const float4*)&hT[k * 64 + ng * 4];
        const u64* pl = (const u64*)&wl[k * H + j0];
        const u64* pr = (const u64*)&wr[k * H + j0];
        u64 l0 = pl[0], l1 = pl[1], r0 = pr[0], r1 = pr[1];
        u64 x0 = pack2(xv.x, xv.x), x1 = pack2(xv.y, xv.y);
        u64 x2 = pack2(xv.z, xv.z), x3 = pack2(xv.w, xv.w);
        al[0] = ffma2(x0, l0, al[0]); al[1] = ffma2(x0, l1, al[1]);
        al[2] = ffma2(x1, l0, al[2]); al[3] = ffma2(x1, l1, al[3]);
        al[4] = ffma2(x2, l0, al[4]); al[5] = ffma2(x2, l1, al[5]);
        al[6] = ffma2(x3, l0, al[6]); al[7] = ffma2(x3, l1, al[7]);
        ar[0] = ffma2(x0, r0, ar[0]); ar[1] = ffma2(x0, r1, ar[1]);
        ar[2] = ffma2(x1, r0, ar[2]); ar[3] = ffma2(x1, r1, ar[3]);
        ar[4] = ffma2(x2, r0, ar[4]); ar[5] = ffma2(x2, r1, ar[5]);
        ar[6] = ffma2(x3, r0, ar[6]); ar[7] = ffma2(x3, r1, ar[7]);
    }

    float4 bb = *(const float4*)&bl[j0];
    int nb0 = blockIdx.x * 64 + ng * 4;
    #pragma unroll
    for (int c = 0; c < 4; c++) {
        int n2 = nb0 + c;
        if (n2 < N) {
            size_t o = (size_t)n2 * H + j0;
            float2 lo = unpack2(al[c * 2]), hi = unpack2(al[c * 2 + 1]);
            *(float4*)&g_xl[o] = make_float4(lo.x, lo.y, hi.x, hi.y);
            float2 ro = unpack2(ar[c * 2]), rh = unpack2(ar[c * 2 + 1]);
            *(float4*)&g_xb[o] = make_float4(ro.x + bb.x, ro.y + bb.y, rh.x + bb.z, rh.y + bb.w);
        }
    }
}

// ------------------------------------------------- h1 = relu(s/cnt + xb); g_hq = h1 @ Wo1
__global__ void __launch_bounds__(256) k_node_fin(const float* __restrict__ Wo1, int N) {
    __shared__ float hT[H * 64];    // 16KB
    __shared__ float ws[H * H];     // 16KB
    int tid = threadIdx.x;
    #pragma unroll
    for (int i = 0; i < 4; i++)
        ((float4*)ws)[tid + i * 256] = ((const float4*)Wo1)[tid + i * 256];
    {
        int n_l = tid >> 2, part = tid & 3, jp = part * 16;
        int n = blockIdx.x * 64 + n_l;
        if (n < N) {
            float inv = 1.0f / fmaxf(g_cnt[n], 1.0f);
            size_t o = (size_t)n * H + jp;
            #pragma unroll
            for (int c = 0; c < 4; c++) {
                float4 s4 = *(const float4*)&g_s[o + c * 4];
                float4 b4 = *(const float4*)&g_xb[o + c * 4];
                int jb = jp + c * 4;
                hT[(jb + 0) * 64 + n_l] = fmaxf(fmaf(s4.x, inv, b4.x), 0.f);
                hT[(jb + 1) * 64 + n_l] = fmaxf(fmaf(s4.y, inv, b4.y), 0.f);
                hT[(jb + 2) * 64 + n_l] = fmaxf(fmaf(s4.z, inv, b4.z), 0.f);
                hT[(jb + 3) * 64 + n_l] = fmaxf(fmaf(s4.w, inv, b4.w), 0.f);
            }
        } else {
            #pragma unroll
            for (int c = 0; c < 16; c++) hT[(jp + c) * 64 + n_l] = 0.f;
        }
    }
    __syncthreads();

    int ng = tid >> 4, jg = tid & 15, j0 = jg * 4;
    u64 ac[8];
    #pragma unroll
    for (int c = 0; c < 8; c++) ac[c] = 0;

    #pragma unroll 4
    for (int k = 0; k < H; k++) {
        float4 xv = *(const float4*)&hT[k * 64 + ng * 4];
        const u64* pw = (const u64*)&ws[k * H + j0];
        u64 w0 = pw[0], w1 = pw[1];
        u64 x0 = pack2(xv.x, xv.x), x1 = pack2(xv.y, xv.y);
        u64 x2 = pack2(xv.z, xv.z), x3 = pack2(xv.w, xv.w);
        ac[0] = ffma2(x0, w0, ac[0]); ac[1] = ffma2(x0, w1, ac[1]);
        ac[2] = ffma2(x1, w0, ac[2]); ac[3] = ffma2(x1, w1, ac[3]);
        ac[4] = ffma2(x2, w0, ac[4]); ac[5] = ffma2(x2, w1, ac[5]);
        ac[6] = ffma2(x3, w0, ac[6]); ac[7] = ffma2(x3, w1, ac[7]);
    }

    int nb0 = blockIdx.x * 64 + ng * 4;
    #pragma unroll
    for (int c = 0; c < 4; c++) {
        int n2 = nb0 + c;
        if (n2 < N) {
            float2 lo = unpack2(ac[c * 2]), hi = unpack2(ac[c * 2 + 1]);
            *(float4*)&g_hq[(size_t)n2 * H + j0] = make_float4(lo.x, lo.y, hi.x, hi.y);
        }
    }
}

// ------------------------------------------------- per-edge head: block-tiled GEMM
// 128 edges/block, 256 threads. Phase A (ffma2): z[k][e]=relu(ea.We1+be1) into smem.
// Phase B: thread owns 4 edges x 8 j; 3 LDS feed 16 ffma2 per k-step.
struct __align__(16) EdgeSmem {
    float zs[H][TE];
    float w2os[H][H];
    float we1t[H][16];
    float be1s[H];
    float b2os[H];
    float wo2s[H];
    int   sidx[TE];
    int   tidx[TE];
    float bo2s;
};

__global__ void __launch_bounds__(256) k_edge(const int* __restrict__ ei, int E,
                                              const float* __restrict__ edge_attr,
                                              const float* __restrict__ We1,
                                              const float* __restrict__ be1,
                                              const float* __restrict__ Wo2,
                                              const float* __restrict__ bo2,
                                              float* __restrict__ out) {
    extern __shared__ char smem_raw[];
    EdgeSmem* S = (EdgeSmem*)smem_raw;
    int tid = threadIdx.x;
    long long e_base = (long long)blockIdx.x * TE;

    #pragma unroll
    for (int i = 0; i < (H * H / 4) / 256; i++)
        ((float4*)S->w2os)[tid + i * 256] = ((const float4*)g_W2o)[tid + i * 256];
    #pragma unroll
    for (int r = 0; r < 4; r++) {
        int idx = tid + r * 256;
        int kk = idx >> 4, ii = idx & 15;
        S->we1t[kk][ii] = We1[ii * H + kk];
    }
    if (tid < H) {
        S->be1s[tid] = be1[tid];
        S->b2os[tid] = g_b2o[tid];
        S->wo2s[tid] = Wo2[tid];
    }
    if (tid == 0) S->bo2s = bo2[0];
    if (tid < TE) {
        long long e = e_base + tid;
        S->sidx[tid] = (e < E) ? ei[e] : 0;
    } else {
        int el = tid - TE;
        long long e = e_base + el;
        S->tidx[el] = (e < E) ? ei[(size_t)E + e] : 0;
    }
    __syncthreads();

    // Phase A (ffma2): 2 threads per edge, 32 k each
    {
        int th = tid >> 7;
        int el = tid & (TE - 1);
        long long e = e_base + el;
        u64 ea2[8];
        if (e < E) {
            const float4* eap = (const float4*)(edge_attr + (size_t)e * 16);
            #pragma unroll
            for (int c = 0; c < 4; c++) {
                float4 v = eap[c];
                ea2[2 * c + 0] = pack2(v.x, v.y);
                ea2[2 * c + 1] = pack2(v.z, v.w);
            }
        } else {
            #pragma unroll
            for (int c = 0; c < 8; c++) ea2[c] = 0;
        }
        int k0 = th * 32;
        #pragma unroll 4
        for (int k = k0; k < k0 + 32; k++) {
            u64 z2 = pack2(S->be1s[k], 0.0f);
            const u64* wp = (const u64*)S->we1t[k];
            #pragma unroll
            for (int q = 0; q < 8; q++) z2 = ffma2(ea2[q], wp[q], z2);
            float2 zz = unpack2(z2);
            S->zs[k][el] = fmaxf(zz.x + zz.y, 0.f);
        }
    }
    __syncthreads();

    int eg = tid >> 3;
    int jg = tid & 7;
    int e0 = eg * 4;
    int j0 = jg * 8;

    u64 acc2[16];
    #pragma unroll
    for (int i = 0; i < 4; i++) {
        int s = S->sidx[e0 + i];
        int t = S->tidx[e0 + i];
        const float4* ps = (const float4*)&g_hq[(size_t)s * H + j0];
        const float4* pt = (const float4*)&g_hq[(size_t)t * H + j0];
        float4 a0 = ps[0], a1 = ps[1], b0 = pt[0], b1 = pt[1];
        float4 c0 = *(const float4*)&S->b2os[j0];
        float4 c1 = *(const float4*)&S->b2os[j0 + 4];
        acc2[i*4+0] = pack2(a0.x + b0.x + c0.x, a0.y + b0.y + c0.y);
        acc2[i*4+1] = pack2(a0.z + b0.z + c0.z, a0.w + b0.w + c0.w);
        acc2[i*4+2] = pack2(a1.x + b1.x + c1.x, a1.y + b1.y + c1.y);
        acc2[i*4+3] = pack2(a1.z + b1.z + c1.z, a1.w + b1.w + c1.w);
    }

    #pragma unroll 2
    for (int k = 0; k < H; k++) {
        float4 zv = *(const float4*)&S->zs[k][e0];
        const u64* wp = (const u64*)&S->w2os[k][j0];
        u64 w0 = wp[0], w1 = wp[1], w2 = wp[2], w3 = wp[3];
        u64 z0 = pack2(zv.x, zv.x), z1 = pack2(zv.y, zv.y);
        u64 z2 = pack2(zv.z, zv.z), z3 = pack2(zv.w, zv.w);
        acc2[0]  = ffma2(z0, w0, acc2[0]);  acc2[1]  = ffma2(z0, w1, acc2[1]);
        acc2[2]  = ffma2(z0, w2, acc2[2]);  acc2[3]  = ffma2(z0, w3, acc2[3]);
        acc2[4]  = ffma2(z1, w0, acc2[4]);  acc2[5]  = ffma2(z1, w1, acc2[5]);
        acc2[6]  = ffma2(z1, w2, acc2[6]);  acc2[7]  = ffma2(z1, w3, acc2[7]);
        acc2[8]  = ffma2(z2, w0, acc2[8]);  acc2[9]  = ffma2(z2, w1, acc2[9]);
        acc2[10] = ffma2(z2, w2, acc2[10]); acc2[11] = ffma2(z2, w3, acc2[11]);
        acc2[12] = ffma2(z3, w0, acc2[12]); acc2[13] = ffma2(z3, w1, acc2[13]);
        acc2[14] = ffma2(z3, w2, acc2[14]); acc2[15] = ffma2(z3, w3, acc2[15]);
    }

    float r[4];
    #pragma unroll
    for (int i = 0; i < 4; i++) {
        float po = 0.f;
        #pragma unroll
        for (int p = 0; p < 4; p++) {
            float2 a = unpack2(acc2[i*4+p]);
            po = fmaf(fmaxf(a.x, 0.f), S->wo2s[j0 + 2*p + 0], po);
            po = fmaf(fmaxf(a.y, 0.f), S->wo2s[j0 + 2*p + 1], po);
        }
        po += __shfl_xor_sync(0xffffffffu, po, 4);
        po += __shfl_xor_sync(0xffffffffu, po, 2);
        po += __shfl_xor_sync(0xffffffffu, po, 1);
        r[i] = po;
    }
    if (jg == 0) {
        float b = S->bo2s;
        #pragma unroll
        for (int i = 0; i < 4; i++)
            r[i] = 1.0f / (1.0f + expf(-(r[i] + b)));
        long long e = e_base + e0;
        if (e + 3 < E) {
            *(float4*)&out[e] = make_float4(r[0], r[1], r[2], r[3]);
        } else {
            #pragma unroll
            for (int i = 0; i < 4; i++)
                if (e + i < E) out[e + i] = r[i];
        }
    }
}

// ----------------------------------------------------------------------------
extern "C" void kernel_launch(void* const* d_in, const int* in_sizes, int n_in,
                              void* d_out, int out_size) {
    const float* x   = (const float*)d_in[0];
    const int*   ei  = (const int*)d_in[1];       // int32 (JAX x64 disabled)
    const float* eat = (const float*)d_in[2];
    const float* We1 = (const float*)d_in[3];
    const float* be1 = (const float*)d_in[4];
    const float* We2 = (const float*)d_in[5];
    const float* be2 = (const float*)d_in[6];
    const float* Wl0 = (const float*)d_in[7];
    const float* bl0 = (const float*)d_in[8];
    const float* Wr0 = (const float*)d_in[9];
    const float* Wl1 = (const float*)d_in[10];
    const float* bl1 = (const float*)d_in[11];
    const float* Wr1 = (const float*)d_in[12];
    const float* Wo1 = (const float*)d_in[13];
    const float* bo1 = (const float*)d_in[14];
    const float* Wo2 = (const float*)d_in[15];
    const float* bo2 = (const float*)d_in[16];

    int N = in_sizes[0] / FI;          // 100000
    if (N > NN) N = NN;
    int E = in_sizes[1] / 2;           // 1000000
    float* out = (float*)d_out;

    int nb64 = (N + 63) / 64;
    unsigned sth = (unsigned)E * 16u;
    unsigned sblocks = (sth + 255u) / 256u;

    int smem_mid  = (H * 64 + H * H + H * H) * 4;      // 48KB
    int smem_edge = (int)sizeof(EdgeSmem);
    cudaFuncSetAttribute(k_node_mid,  cudaFuncAttributeMaxDynamicSharedMemorySize, smem_mid);
    cudaFuncSetAttribute(k_edge,      cudaFuncAttributeMaxDynamicSharedMemorySize, smem_edge);

    k_prep<<<H + 1, H>>>(We2, Wo1, be2, bo1);
    k_node_dual<<<nb64, 256>>>(x, Wl0, Wr0, bl0, N);
    k_scatter<<<sblocks, 256>>>(ei, E, 1);
    k_node_mid<<<nb64, 256, smem_mid>>>(Wl1, Wr1, bl1, N);
    k_scatter<<<sblocks, 256>>>(ei, E, 0);
    k_node_fin<<<nb64, 256>>>(Wo1, N);
    k_edge<<<(E + TE - 1) / TE, 256, smem_edge>>>(ei, E, eat, We1, be1, Wo2, bo2, out);
}

// round 16
// speedup vs baseline: 1.9925x; 1.2325x over previous
#include <cuda_runtime.h>
#include <cstdint>
#include <math.h>

#define NN 100000
#define FI 128
#define H  64
#define TE 128   // edges per block in k_edge
#define ZST 136  // zs row stride (TE + 8 pad: stride%32==8 -> conflict-free frags)
#define WST 72   // w2os row stride (H + 8 pad)

typedef unsigned long long u64;

__device__ __forceinline__ u64 ffma2(u64 a, u64 b, u64 c) {
    u64 d;
    asm("fma.rn.f32x2 %0, %1, %2, %3;" : "=l"(d) : "l"(a), "l"(b), "l"(c));
    return d;
}
__device__ __forceinline__ float2 unpack2(u64 p) {
    float2 f;
    asm("mov.b64 {%0,%1}, %2;" : "=f"(f.x), "=f"(f.y) : "l"(p));
    return f;
}
__device__ __forceinline__ u64 pack2(float lo, float hi) {
    u64 p;
    asm("mov.b64 %0, {%1,%2};" : "=l"(p) : "f"(lo), "f"(hi));
    return p;
}
// m16n8k8 tf32 warp MMA (sm_80+ fragment layout)
__device__ __forceinline__ void mma_tf32(float& d0, float& d1, float& d2, float& d3,
                                         unsigned a0, unsigned a1, unsigned a2, unsigned a3,
                                         unsigned b0, unsigned b1) {
    asm("mma.sync.aligned.m16n8k8.row.col.f32.tf32.tf32.f32 "
        "{%0,%1,%2,%3},{%4,%5,%6,%7},{%8,%9},{%0,%1,%2,%3};"
        : "+f"(d0), "+f"(d1), "+f"(d2), "+f"(d3)
        : "r"(a0), "r"(a1), "r"(a2), "r"(a3), "r"(b0), "r"(b1));
}

// Scratch (device globals). 16B-aligned for float4 access.
__device__ __align__(16) float g_xl[(size_t)NN * H];
__device__ __align__(16) float g_xb[(size_t)NN * H];
__device__ __align__(16) float g_s [(size_t)NN * H];
__device__ __align__(16) float g_cnt[NN];
__device__ __align__(16) float g_hq[(size_t)NN * H];
__device__ __align__(16) float g_W2o[H * H];
__device__ __align__(16) float g_b2o[H];

// ---------------------------------------------------------------- prep (parallel)
__global__ void k_prep(const float* __restrict__ We2, const float* __restrict__ Wo1,
                       const float* __restrict__ be2, const float* __restrict__ bo1) {
    int j = threadIdx.x;
    int b = blockIdx.x;
    if (b < H) {
        float acc = 0.f;
        #pragma unroll 8
        for (int k = 0; k < H; k++) acc += We2[b * H + k] * Wo1[k * H + j];
        g_W2o[b * H + j] = acc;
    } else {
        float acc = bo1[j];
        #pragma unroll 8
        for (int k = 0; k < H; k++) acc += be2[k] * Wo1[k * H + j];
        g_b2o[j] = acc;
    }
}

// ------------------------------------------------- fused node linear (R15 baseline form)
__global__ void __launch_bounds__(256) k_node_dual(const float* __restrict__ x,
                                                   const float* __restrict__ Wl,
                                                   const float* __restrict__ Wr,
                                                   const float* __restrict__ bl, int N) {
    __shared__ float xT[64 * 64];
    __shared__ float wl[64 * H];
    __shared__ float wr[64 * H];
    int tid = threadIdx.x;
    int ng = tid >> 4, jg = tid & 15, j0 = jg * 4;
    int nbase = blockIdx.x * 64;

    u64 al[8], ar[8];
    #pragma unroll
    for (int c = 0; c < 8; c++) { al[c] = 0; ar[c] = 0; }

    #pragma unroll
    for (int ch = 0; ch < 2; ch++) {
        __syncthreads();
        #pragma unroll
        for (int i = 0; i < 4; i++) {
            ((float4*)wl)[tid + i * 256] = ((const float4*)(Wl + ch * 64 * H))[tid + i * 256];
            ((float4*)wr)[tid + i * 256] = ((const float4*)(Wr + ch * 64 * H))[tid + i * 256];
        }
        {
            int n_l = tid & 63, q = tid >> 6;
            int n = nbase + n_l;
            #pragma unroll
            for (int r = 0; r < 4; r++) {
                int i0 = q * 16 + r * 4;
                float4 v = make_float4(0.f, 0.f, 0.f, 0.f);
                if (n < N) v = *(const float4*)&x[(size_t)n * FI + ch * 64 + i0];
                xT[(i0 + 0) * 64 + n_l] = v.x;
                xT[(i0 + 1) * 64 + n_l] = v.y;
                xT[(i0 + 2) * 64 + n_l] = v.z;
                xT[(i0 + 3) * 64 + n_l] = v.w;
            }
        }
        __syncthreads();

        #pragma unroll 4
        for (int i = 0; i < 64; i++) {
            float4 xv = *(const float4*)&xT[i * 64 + ng * 4];
            const u64* pl = (const u64*)&wl[i * H + j0];
            const u64* pr = (const u64*)&wr[i * H + j0];
            u64 l0 = pl[0], l1 = pl[1], r0 = pr[0], r1 = pr[1];
            u64 x0 = pack2(xv.x, xv.x), x1 = pack2(xv.y, xv.y);
            u64 x2 = pack2(xv.z, xv.z), x3 = pack2(xv.w, xv.w);
            al[0] = ffma2(x0, l0, al[0]); al[1] = ffma2(x0, l1, al[1]);
            al[2] = ffma2(x1, l0, al[2]); al[3] = ffma2(x1, l1, al[3]);
            al[4] = ffma2(x2, l0, al[4]); al[5] = ffma2(x2, l1, al[5]);
            al[6] = ffma2(x3, l0, al[6]); al[7] = ffma2(x3, l1, al[7]);
            ar[0] = ffma2(x0, r0, ar[0]); ar[1] = ffma2(x0, r1, ar[1]);
            ar[2] = ffma2(x1, r0, ar[2]); ar[3] = ffma2(x1, r1, ar[3]);
            ar[4] = ffma2(x2, r0, ar[4]); ar[5] = ffma2(x2, r1, ar[5]);
            ar[6] = ffma2(x3, r0, ar[6]); ar[7] = ffma2(x3, r1, ar[7]);
        }
    }

    float4 bb = *(const float4*)&bl[j0];
    int nb0 = nbase + ng * 4;
    #pragma unroll
    for (int c = 0; c < 4; c++) {
        int n2 = nb0 + c;
        if (n2 < N) {
            size_t o = (size_t)n2 * H + j0;
            float2 lo = unpack2(al[c * 2]), hi = unpack2(al[c * 2 + 1]);
            *(float4*)&g_xl[o] = make_float4(lo.x, lo.y, hi.x, hi.y);
            float2 ro = unpack2(ar[c * 2]), rh = unpack2(ar[c * 2 + 1]);
            *(float4*)&g_xb[o] = make_float4(ro.x + bb.x, ro.y + bb.y, rh.x + bb.z, rh.y + bb.w);
            *(float4*)&g_s[o] = make_float4(0.f, 0.f, 0.f, 0.f);
            if (jg == 0) g_cnt[n2] = 0.f;
        }
    }
}

// ------------------------------------------------- edge scatter
__global__ void k_scatter(const int* __restrict__ ei, int E, int do_cnt) {
    unsigned idx = blockIdx.x * 256u + threadIdx.x;
    unsigned e = idx >> 4;
    if (e >= (unsigned)E) return;
    int k4 = (int)(idx & 15u) * 4;
    int s = ei[e];
    int t = ei[(size_t)E + e];
    float4 v = *(const float4*)(g_xl + (size_t)s * H + k4);
    float* p = g_s + (size_t)t * H + k4;
    asm volatile("red.global.add.v4.f32 [%0], {%1,%2,%3,%4};"
                 :: "l"(p), "f"(v.x), "f"(v.y), "f"(v.z), "f"(v.w) : "memory");
    if (do_cnt && k4 == 0) atomicAdd(g_cnt + t, 1.0f);
}

// ------------------------------------------------- h0 = relu(s/cnt + xb); dual project Wl1/Wr1
__global__ void __launch_bounds__(256) k_node_mid(const float* __restrict__ Wl,
                                                  const float* __restrict__ Wr,
                                                  const float* __restrict__ bl, int N) {
    extern __shared__ float sm[];
    float* hT = sm;
    float* wl = sm + H * 64;
    float* wr = wl + H * H;
    int tid = threadIdx.x;
    #pragma unroll
    for (int i = 0; i < 4; i++) {
        ((float4*)wl)[tid + i * 256] = ((const float4*)Wl)[tid + i * 256];
        ((float4*)wr)[tid + i * 256] = ((const float4*)Wr)[tid + i * 256];
    }
    {
        int n_l = tid >> 2, part = tid & 3, jp = part * 16;
        int n = blockIdx.x * 64 + n_l;
        if (n < N) {
            float inv = 1.0f / fmaxf(g_cnt[n], 1.0f);
            size_t o = (size_t)n * H + jp;
            #pragma unroll
            for (int c = 0; c < 4; c++) {
                float4 s4 = *(const float4*)&g_s[o + c * 4];
                float4 b4 = *(const float4*)&g_xb[o + c * 4];
                int jb = jp + c * 4;
                hT[(jb + 0) * 64 + n_l] = fmaxf(fmaf(s4.x, inv, b4.x), 0.f);
                hT[(jb + 1) * 64 + n_l] = fmaxf(fmaf(s4.y, inv, b4.y), 0.f);
                hT[(jb + 2) * 64 + n_l] = fmaxf(fmaf(s4.z, inv, b4.z), 0.f);
                hT[(jb + 3) * 64 + n_l] = fmaxf(fmaf(s4.w, inv, b4.w), 0.f);
                *(float4*)&g_s[o + c * 4] = make_float4(0.f, 0.f, 0.f, 0.f);
            }
        } else {
            #pragma unroll
            for (int c = 0; c < 16; c++) hT[(jp + c) * 64 + n_l] = 0.f;
        }
    }
    __syncthreads();

    int ng = tid >> 4, jg = tid & 15, j0 = jg * 4;
    u64 al[8], ar[8];
    #pragma unroll
    for (int c = 0; c < 8; c++) { al[c] = 0; ar[c] = 0; }

    #pragma unroll 4
    for (int k = 0; k < H; k++) {
        float4 xv = *(const float4*)&hT[k * 64 + ng * 4];
        const u64* pl = (const u64*)&wl[k * H + j0];
        const u64* pr = (const u64*)&wr[k * H + j0];
        u64 l0 = pl[0], l1 = pl[1], r0 = pr[0], r1 = pr[1];
        u64 x0 = pack2(xv.x, xv.x), x1 = pack2(xv.y, xv.y);
        u64 x2 = pack2(xv.z, xv.z), x3 = pack2(xv.w, xv.w);
        al[0] = ffma2(x0, l0, al[0]); al[1] = ffma2(x0, l1, al[1]);
        al[2] = ffma2(x1, l0, al[2]); al[3] = ffma2(x1, l1, al[3]);
        al[4] = ffma2(x2, l0, al[4]); al[5] = ffma2(x2, l1, al[5]);
        al[6] = ffma2(x3, l0, al[6]); al[7] = ffma2(x3, l1, al[7]);
        ar[0] = ffma2(x0, r0, ar[0]); ar[1] = ffma2(x0, r1, ar[1]);
        ar[2] = ffma2(x1, r0, ar[2]); ar[3] = ffma2(x1, r1, ar[3]);
        ar[4] = ffma2(x2, r0, ar[4]); ar[5] = ffma2(x2, r1, ar[5]);
        ar[6] = ffma2(x3, r0, ar[6]); ar[7] = ffma2(x3, r1, ar[7]);
    }

    float4 bb = *(const float4*)&bl[j0];
    int nb0 = blockIdx.x * 64 + ng * 4;
    #pragma unroll
    for (int c = 0; c < 4; c++) {
        int n2 = nb0 + c;
        if (n2 < N) {
            size_t o = (size_t)n2 * H + j0;
            float2 lo = unpack2(al[c * 2]), hi = unpack2(al[c * 2 + 1]);
            *(float4*)&g_xl[o] = make_float4(lo.x, lo.y, hi.x, hi.y);
            float2 ro = unpack2(ar[c * 2]), rh = unpack2(ar[c * 2 + 1]);
            *(float4*)&g_xb[o] = make_float4(ro.x + bb.x, ro.y + bb.y, rh.x + bb.z, rh.y + bb.w);
        }
    }
}

// ------------------------------------------------- h1 = relu(s/cnt + xb); g_hq = h1 @ Wo1
__global__ void __launch_bounds__(256) k_node_fin(const float* __restrict__ Wo1, int N) {
    __shared__ float hT[H * 64];
    __shared__ float ws[H * H];
    int tid = threadIdx.x;
    #pragma unroll
    for (int i = 0; i < 4; i++)
        ((float4*)ws)[tid + i * 256] = ((const float4*)Wo1)[tid + i * 256];
    {
        int n_l = tid >> 2, part = tid & 3, jp = part * 16;
        int n = blockIdx.x * 64 + n_l;
        if (n < N) {
            float inv = 1.0f / fmaxf(g_cnt[n], 1.0f);
            size_t o = (size_t)n * H + jp;
            #pragma unroll
            for (int c = 0; c < 4; c++) {
                float4 s4 = *(const float4*)&g_s[o + c * 4];
                float4 b4 = *(const float4*)&g_xb[o + c * 4];
                int jb = jp + c * 4;
                hT[(jb + 0) * 64 + n_l] = fmaxf(fmaf(s4.x, inv, b4.x), 0.f);
                hT[(jb + 1) * 64 + n_l] = fmaxf(fmaf(s4.y, inv, b4.y), 0.f);
                hT[(jb + 2) * 64 + n_l] = fmaxf(fmaf(s4.z, inv, b4.z), 0.f);
                hT[(jb + 3) * 64 + n_l] = fmaxf(fmaf(s4.w, inv, b4.w), 0.f);
            }
        } else {
            #pragma unroll
            for (int c = 0; c < 16; c++) hT[(jp + c) * 64 + n_l] = 0.f;
        }
    }
    __syncthreads();

    int ng = tid >> 4, jg = tid & 15, j0 = jg * 4;
    u64 ac[8];
    #pragma unroll
    for (int c = 0; c < 8; c++) ac[c] = 0;

    #pragma unroll 4
    for (int k = 0; k < H; k++) {
        float4 xv = *(const float4*)&hT[k * 64 + ng * 4];
        const u64* pw = (const u64*)&ws[k * H + j0];
        u64 w0 = pw[0], w1 = pw[1];
        u64 x0 = pack2(xv.x, xv.x), x1 = pack2(xv.y, xv.y);
        u64 x2 = pack2(xv.z, xv.z), x3 = pack2(xv.w, xv.w);
        ac[0] = ffma2(x0, w0, ac[0]); ac[1] = ffma2(x0, w1, ac[1]);
        ac[2] = ffma2(x1, w0, ac[2]); ac[3] = ffma2(x1, w1, ac[3]);
        ac[4] = ffma2(x2, w0, ac[4]); ac[5] = ffma2(x2, w1, ac[5]);
        ac[6] = ffma2(x3, w0, ac[6]); ac[7] = ffma2(x3, w1, ac[7]);
    }

    int nb0 = blockIdx.x * 64 + ng * 4;
    #pragma unroll
    for (int c = 0; c < 4; c++) {
        int n2 = nb0 + c;
        if (n2 < N) {
            float2 lo = unpack2(ac[c * 2]), hi = unpack2(ac[c * 2 + 1]);
            *(float4*)&g_hq[(size_t)n2 * H + j0] = make_float4(lo.x, lo.y, hi.x, hi.y);
        }
    }
}

// ------------------------------------------------- per-edge head: tf32 tensor-core GEMM
// 128 edges/block, 256 threads (8 warps). Phase A: z into zs (stride ZST).
// Phase B: warp w owns edges w*16..w*16+15, full 64 j, via 64 mma.sync.m16n8k8.tf32.
// Epilogue (exact fp32): D + hq[s]+hq[t]+b2o -> relu -> dot wo2 -> sigmoid.
struct __align__(16) EdgeSmem {
    float zs[H * ZST];      // 34.8 KB  [k][e], stride 136
    float w2os[H * WST];    // 18.4 KB  [k][j], stride 72
    float we1t[H][16];      // 4 KB
    float be1s[H];
    float b2os[H];
    float wo2s[H];
    int   sidx[TE];
    int   tidx[TE];
    float bo2s;
};

__global__ void __launch_bounds__(256) k_edge(const int* __restrict__ ei, int E,
                                              const float* __restrict__ edge_attr,
                                              const float* __restrict__ We1,
                                              const float* __restrict__ be1,
                                              const float* __restrict__ Wo2,
                                              const float* __restrict__ bo2,
                                              float* __restrict__ out) {
    extern __shared__ char smem_raw[];
    EdgeSmem* S = (EdgeSmem*)smem_raw;
    int tid = threadIdx.x;
    long long e_base = (long long)blockIdx.x * TE;

    // stage W2o into padded rows
    for (int idx = tid; idx < H * H; idx += 256) {
        int kk = idx >> 6, jj = idx & 63;
        S->w2os[kk * WST + jj] = g_W2o[idx];
    }
    #pragma unroll
    for (int r = 0; r < 4; r++) {
        int idx = tid + r * 256;
        int kk = idx >> 4, ii = idx & 15;
        S->we1t[kk][ii] = We1[ii * H + kk];
    }
    if (tid < H) {
        S->be1s[tid] = be1[tid];
        S->b2os[tid] = g_b2o[tid];
        S->wo2s[tid] = Wo2[tid];
    }
    if (tid == 0) S->bo2s = bo2[0];
    if (tid < TE) {
        long long e = e_base + tid;
        S->sidx[tid] = (e < E) ? ei[e] : 0;
    } else {
        int el = tid - TE;
        long long e = e_base + el;
        S->tidx[el] = (e < E) ? ei[(size_t)E + e] : 0;
    }
    __syncthreads();

    // Phase A (ffma2): 2 threads per edge, 32 k each; write zs[k*ZST + el]
    {
        int th = tid >> 7;
        int el = tid & (TE - 1);
        long long e = e_base + el;
        u64 ea2[8];
        if (e < E) {
            const float4* eap = (const float4*)(edge_attr + (size_t)e * 16);
            #pragma unroll
            for (int c = 0; c < 4; c++) {
                float4 v = eap[c];
                ea2[2 * c + 0] = pack2(v.x, v.y);
                ea2[2 * c + 1] = pack2(v.z, v.w);
            }
        } else {
            #pragma unroll
            for (int c = 0; c < 8; c++) ea2[c] = 0;
        }
        int k0 = th * 32;
        #pragma unroll 4
        for (int k = k0; k < k0 + 32; k++) {
            u64 z2 = pack2(S->be1s[k], 0.0f);
            const u64* wp = (const u64*)S->we1t[k];
            #pragma unroll
            for (int q = 0; q < 8; q++) z2 = ffma2(ea2[q], wp[q], z2);
            float2 zz = unpack2(z2);
            S->zs[k * ZST + el] = fmaxf(zz.x + zz.y, 0.f);
        }
    }
    __syncthreads();

    // Phase B: tensor cores. warp w: edges e0=w*16 .. e0+15, all 64 j.
    int w = tid >> 5;
    int lane = tid & 31;
    int e0 = w * 16;
    int qr = lane >> 2;        // 0..7 (row offset within fragment)
    int qc = lane & 3;         // 0..3 (col offset within fragment)

    float D[32];               // 8 j-tiles x 4 regs
    #pragma unroll
    for (int c = 0; c < 32; c++) D[c] = 0.f;

    #pragma unroll
    for (int kk = 0; kk < 8; kk++) {
        int kb = kk * 8;
        unsigned a0 = __float_as_uint(S->zs[(kb + qc)     * ZST + e0 + qr]);
        unsigned a1 = __float_as_uint(S->zs[(kb + qc)     * ZST + e0 + qr + 8]);
        unsigned a2 = __float_as_uint(S->zs[(kb + qc + 4) * ZST + e0 + qr]);
        unsigned a3 = __float_as_uint(S->zs[(kb + qc + 4) * ZST + e0 + qr + 8]);
        #pragma unroll
        for (int jt = 0; jt < 8; jt++) {
            unsigned b0 = __float_as_uint(S->w2os[(kb + qc)     * WST + jt * 8 + qr]);
            unsigned b1 = __float_as_uint(S->w2os[(kb + qc + 4) * WST + jt * 8 + qr]);
            mma_tf32(D[jt*4+0], D[jt*4+1], D[jt*4+2], D[jt*4+3], a0, a1, a2, a3, b0, b1);
        }
    }

    // Epilogue: this thread holds D for edges eA=e0+qr, eB=eA+8 at cols jt*8+2*qc, +1.
    int eA = e0 + qr, eB = eA + 8;
    int sA = S->sidx[eA], tA = S->tidx[eA];
    int sB = S->sidx[eB], tB = S->tidx[eB];
    const float* hsA = &g_hq[(size_t)sA * H];
    const float* htA = &g_hq[(size_t)tA * H];
    const float* hsB = &g_hq[(size_t)sB * H];
    const float* htB = &g_hq[(size_t)tB * H];

    float sumA = 0.f, sumB = 0.f;
    #pragma unroll
    for (int jt = 0; jt < 8; jt++) {
        int c0 = jt * 8 + 2 * qc;
        float2 b2 = *(const float2*)&S->b2os[c0];
        float2 w2 = *(const float2*)&S->wo2s[c0];
        float2 gsA = *(const float2*)&hsA[c0];
        float2 gtA = *(const float2*)&htA[c0];
        float2 gsB = *(const float2*)&hsB[c0];
        float2 gtB = *(const float2*)&htB[c0];
        sumA = fmaf(fmaxf(D[jt*4+0] + gsA.x + gtA.x + b2.x, 0.f), w2.x, sumA);
        sumA = fmaf(fmaxf(D[jt*4+1] + gsA.y + gtA.y + b2.y, 0.f), w2.y, sumA);
        sumB = fmaf(fmaxf(D[jt*4+2] + gsB.x + gtB.x + b2.x, 0.f), w2.x, sumB);
        sumB = fmaf(fmaxf(D[jt*4+3] + gsB.y + gtB.y + b2.y, 0.f), w2.y, sumB);
    }
    // reduce over the 4 lanes (qc) sharing each edge row
    sumA += __shfl_xor_sync(0xffffffffu, sumA, 1);
    sumA += __shfl_xor_sync(0xffffffffu, sumA, 2);
    sumB += __shfl_xor_sync(0xffffffffu, sumB, 1);
    sumB += __shfl_xor_sync(0xffffffffu, sumB, 2);

    if (qc == 0) {
        float b = S->bo2s;
        long long geA = e_base + eA, geB = e_base + eB;
        if (geA < E) out[geA] = 1.0f / (1.0f + expf(-(sumA + b)));
        if (geB < E) out[geB] = 1.0f / (1.0f + expf(-(sumB + b)));
    }
}

// ----------------------------------------------------------------------------
extern "C" void kernel_launch(void* const* d_in, const int* in_sizes, int n_in,
                              void* d_out, int out_size) {
    const float* x   = (const float*)d_in[0];
    const int*   ei  = (const int*)d_in[1];       // int32 (JAX x64 disabled)
    const float* eat = (const float*)d_in[2];
    const float* We1 = (const float*)d_in[3];
    const float* be1 = (const float*)d_in[4];
    const float* We2 = (const float*)d_in[5];
    const float* be2 = (const float*)d_in[6];
    const float* Wl0 = (const float*)d_in[7];
    const float* bl0 = (const float*)d_in[8];
    const float* Wr0 = (const float*)d_in[9];
    const float* Wl1 = (const float*)d_in[10];
    const float* bl1 = (const float*)d_in[11];
    const float* Wr1 = (const float*)d_in[12];
    const float* Wo1 = (const float*)d_in[13];
    const float* bo1 = (const float*)d_in[14];
    const float* Wo2 = (const float*)d_in[15];
    const float* bo2 = (const float*)d_in[16];

    int N = in_sizes[0] / FI;          // 100000
    if (N > NN) N = NN;
    int E = in_sizes[1] / 2;           // 1000000
    float* out = (float*)d_out;

    int nb64 = (N + 63) / 64;
    unsigned sth = (unsigned)E * 16u;
    unsigned sblocks = (sth + 255u) / 256u;

    int smem_mid  = (H * 64 + H * H + H * H) * 4;      // 48KB
    int smem_edge = (int)sizeof(EdgeSmem);
    cudaFuncSetAttribute(k_node_mid,  cudaFuncAttributeMaxDynamicSharedMemorySize, smem_mid);
    cudaFuncSetAttribute(k_edge,      cudaFuncAttributeMaxDynamicSharedMemorySize, smem_edge);

    k_prep<<<H + 1, H>>>(We2, Wo1, be2, bo1);
    k_node_dual<<<nb64, 256>>>(x, Wl0, Wr0, bl0, N);
    k_scatter<<<sblocks, 256>>>(ei, E, 1);
    k_node_mid<<<nb64, 256, smem_mid>>>(Wl1, Wr1, bl1, N);
    k_scatter<<<sblocks, 256>>>(ei, E, 0);
    k_node_fin<<<nb64, 256>>>(Wo1, N);
    k_edge<<<(E + TE - 1) / TE, 256, smem_edge>>>(ei, E, eat, We1, be1, Wo2, bo2, out);
}